// round 3
// baseline (speedup 1.0000x reference)
#include <cuda_runtime.h>
#include <cstdint>

// ============================================================================
// EdgeClassifier: out = relu([emb[h], emb[t]] @ W1^T + b1) @ W2^T + b2
// E=500000, D=128, HIDDEN=256, NUM_CLASSES=32, fp32 in/out.
// Tensor path: mma.sync.m16n8k8 tf32 (tcgen05 unavailable: harness compiles
// through compute_103 virtual arch, which rejects sm_103a-only PTX).
// ============================================================================

#define TILE_M 128
#define DIMD   128
#define HID    256
#define NCLS   32

#define SAW 260          // A / A2 / W2 smem row stride in floats (pad 4)
#define SBW 68           // W1-chunk smem row stride in floats (64 + pad 4)

// SMEM byte offsets
#define SM_B1   0                          // 256 floats
#define SM_B2   1024                       // 32 floats
#define SM_A    2048                       // 128 x 260 u32 = 133120 B
#define SM_B    (2048 + TILE_M * SAW * 4)  // 256 x 68 u32 = 69632 B
#define SM_TOTAL (SM_B + 256 * SBW * 4)    // 204800 B

__device__ int g_is64;

__device__ __forceinline__ uint32_t f2tf32(float f) {
    uint32_t r;
    asm("cvt.rna.tf32.f32 %0, %1;" : "=r"(r) : "f"(f));
    return r;
}

__device__ __forceinline__ void mma8(float* c, const uint32_t* a,
                                     uint32_t b0, uint32_t b1) {
    asm volatile(
        "mma.sync.aligned.m16n8k8.row.col.f32.tf32.tf32.f32 "
        "{%0,%1,%2,%3}, {%4,%5,%6,%7}, {%8,%9}, {%0,%1,%2,%3};"
        : "+f"(c[0]), "+f"(c[1]), "+f"(c[2]), "+f"(c[3])
        : "r"(a[0]), "r"(a[1]), "r"(a[2]), "r"(a[3]), "r"(b0), "r"(b1));
}

// Detect int64 vs int32 edge_index: high words of first 128 int64 values are
// all zero iff int64 (indices < 2^31). Deterministic, alloc-free.
__global__ void detect_idx_kernel(const unsigned int* __restrict__ p) {
    unsigned int acc = 0;
    for (int i = 1; i < 256; i += 2) acc |= p[i];
    g_is64 = (acc == 0u) ? 1 : 0;
}

// ============================================================================
__global__ __launch_bounds__(256, 1)
void edge_mlp_kernel(const float* __restrict__ emb,
                     const void*  __restrict__ eidx,
                     const float* __restrict__ W1,
                     const float* __restrict__ b1,
                     const float* __restrict__ W2,
                     const float* __restrict__ b2,
                     float* __restrict__ out,
                     int E) {
    extern __shared__ char smem[];
    float*    sb1 = (float*)(smem + SM_B1);
    float*    sb2 = (float*)(smem + SM_B2);
    uint32_t* Asm = (uint32_t*)(smem + SM_A);
    uint32_t* Bsm = (uint32_t*)(smem + SM_B);

    const int tid  = threadIdx.x;
    const int wid  = tid >> 5;
    const int lane = tid & 31;
    const int g    = lane >> 2;   // groupID   (0..7)
    const int t    = lane & 3;    // tid-in-group (0..3)
    const int tile = blockIdx.x;
    const int is64 = g_is64;

    sb1[tid] = b1[tid];
    if (tid < NCLS) sb2[tid] = b2[tid];

    // ---- Gather A[128][256]: 256 row-halves, one warp row-half per iter ----
    for (int rh = wid; rh < 2 * TILE_M; rh += 8) {
        const int r = rh >> 1, half = rh & 1;
        const int e = tile * TILE_M + r;
        float4 v = make_float4(0.f, 0.f, 0.f, 0.f);
        if (e < E) {
            const long long ofs = half ? (long long)E + e : (long long)e;
            const long long node = is64 ? ((const long long*)eidx)[ofs]
                                        : (long long)((const int*)eidx)[ofs];
            v = ((const float4*)(emb + node * DIMD))[lane];
        }
        uint4 u = make_uint4(f2tf32(v.x), f2tf32(v.y), f2tf32(v.z), f2tf32(v.w));
        *(uint4*)(Asm + r * SAW + half * 128 + lane * 4) = u;
    }
    __syncthreads();

    // ---- GEMM1: D1[128,256] = A @ W1^T; full acc in registers -------------
    const int mbase = (wid & 3) * 32;
    const int nbase = (wid >> 2) * 128;

    float acc[2][16][4];
    #pragma unroll
    for (int mt = 0; mt < 2; mt++)
        #pragma unroll
        for (int nt = 0; nt < 16; nt++)
            #pragma unroll
            for (int j = 0; j < 4; j++) acc[mt][nt][j] = 0.f;

    #pragma unroll 1
    for (int kc = 0; kc < 4; kc++) {
        // Stage W1[:, kc*64 .. +64) -> Bsm[n][kk], tf32-converted.
        {
            const float4* wrow = (const float4*)(W1 + tid * (2 * DIMD) + kc * 64);
            uint32_t* brow = Bsm + tid * SBW;
            #pragma unroll
            for (int j = 0; j < 16; j++) {
                float4 w = wrow[j];
                *(uint4*)(brow + j * 4) = make_uint4(f2tf32(w.x), f2tf32(w.y),
                                                     f2tf32(w.z), f2tf32(w.w));
            }
        }
        __syncthreads();

        #pragma unroll 1
        for (int s = 0; s < 8; s++) {
            const int k0 = s * 8;                 // local k in chunk
            const int ka = kc * 64 + k0;          // global k for A
            uint32_t af[2][4];
            #pragma unroll
            for (int mt = 0; mt < 2; mt++) {
                const int r = mbase + mt * 16;
                af[mt][0] = Asm[(r + g)     * SAW + ka + t];
                af[mt][1] = Asm[(r + g + 8) * SAW + ka + t];
                af[mt][2] = Asm[(r + g)     * SAW + ka + t + 4];
                af[mt][3] = Asm[(r + g + 8) * SAW + ka + t + 4];
            }
            #pragma unroll
            for (int nt = 0; nt < 16; nt++) {
                const int n = nbase + nt * 8 + g;
                const uint32_t b0 = Bsm[n * SBW + k0 + t];
                const uint32_t b1r = Bsm[n * SBW + k0 + t + 4];
                mma8(acc[0][nt], af[0], b0, b1r);
                mma8(acc[1][nt], af[1], b0, b1r);
            }
        }
        __syncthreads();
    }

    // ---- Epilogue1: A2 = tf32(relu(D1 + b1)), in place over A -------------
    #pragma unroll
    for (int mt = 0; mt < 2; mt++) {
        #pragma unroll
        for (int nt = 0; nt < 16; nt++) {
            const int r0  = mbase + mt * 16 + g;
            const int col = nbase + nt * 8 + t * 2;
            const float bi0 = sb1[col], bi1 = sb1[col + 1];
            float* c = acc[mt][nt];
            uint2 lo, hi;
            lo.x = f2tf32(fmaxf(c[0] + bi0, 0.f));
            lo.y = f2tf32(fmaxf(c[1] + bi1, 0.f));
            hi.x = f2tf32(fmaxf(c[2] + bi0, 0.f));
            hi.y = f2tf32(fmaxf(c[3] + bi1, 0.f));
            *(uint2*)(Asm + r0 * SAW + col)       = lo;
            *(uint2*)(Asm + (r0 + 8) * SAW + col) = hi;
        }
    }
    // Stage W2[32][256] -> Bsm (stride SAW), tf32.
    {
        const int rw = tid >> 3;                 // 0..31
        const float4* wrow = (const float4*)(W2 + rw * HID) + (tid & 7);
        uint32_t* brow = Bsm + rw * SAW + (tid & 7) * 4;
        #pragma unroll
        for (int j = 0; j < 8; j++) {
            float4 w = wrow[j * 8];
            *(uint4*)(brow + j * 32) = make_uint4(f2tf32(w.x), f2tf32(w.y),
                                                  f2tf32(w.z), f2tf32(w.w));
        }
    }
    __syncthreads();

    // ---- GEMM2: D2[128,32] = A2 @ W2^T (warps 0-3) + epilogue2 ------------
    if (wid < 4) {
        const int m2 = wid * 32;
        float acc2[2][4][4];
        #pragma unroll
        for (int mt = 0; mt < 2; mt++)
            #pragma unroll
            for (int nt = 0; nt < 4; nt++)
                #pragma unroll
                for (int j = 0; j < 4; j++) acc2[mt][nt][j] = 0.f;

        #pragma unroll 1
        for (int s = 0; s < 32; s++) {
            const int k0 = s * 8;
            uint32_t af[2][4];
            #pragma unroll
            for (int mt = 0; mt < 2; mt++) {
                const int r = m2 + mt * 16;
                af[mt][0] = Asm[(r + g)     * SAW + k0 + t];
                af[mt][1] = Asm[(r + g + 8) * SAW + k0 + t];
                af[mt][2] = Asm[(r + g)     * SAW + k0 + t + 4];
                af[mt][3] = Asm[(r + g + 8) * SAW + k0 + t + 4];
            }
            #pragma unroll
            for (int nt = 0; nt < 4; nt++) {
                const int n = nt * 8 + g;
                const uint32_t b0 = Bsm[n * SAW + k0 + t];
                const uint32_t b1r = Bsm[n * SAW + k0 + t + 4];
                mma8(acc2[0][nt], af[0], b0, b1r);
                mma8(acc2[1][nt], af[1], b0, b1r);
            }
        }

        #pragma unroll
        for (int mt = 0; mt < 2; mt++) {
            #pragma unroll
            for (int nt = 0; nt < 4; nt++) {
                const int col = nt * 8 + t * 2;
                const float bi0 = sb2[col], bi1 = sb2[col + 1];
                float* c = acc2[mt][nt];
                const int mr0 = tile * TILE_M + m2 + mt * 16 + g;
                if (mr0 < E) {
                    float2 o = make_float2(c[0] + bi0, c[1] + bi1);
                    *(float2*)(out + (size_t)mr0 * NCLS + col) = o;
                }
                if (mr0 + 8 < E) {
                    float2 o = make_float2(c[2] + bi0, c[3] + bi1);
                    *(float2*)(out + (size_t)(mr0 + 8) * NCLS + col) = o;
                }
            }
        }
    }
}

// ============================================================================
extern "C" void kernel_launch(void* const* d_in, const int* in_sizes, int n_in,
                              void* d_out, int out_size) {
    const float* emb  = (const float*)d_in[0];
    const void*  eidx = d_in[1];
    const float* W1   = (const float*)d_in[2];
    const float* b1   = (const float*)d_in[3];
    const float* W2   = (const float*)d_in[4];
    const float* b2   = (const float*)d_in[5];
    float* out = (float*)d_out;

    const int E = in_sizes[1] / 2;
    const int tiles = (E + TILE_M - 1) / TILE_M;

    cudaFuncSetAttribute(edge_mlp_kernel,
                         cudaFuncAttributeMaxDynamicSharedMemorySize, SM_TOTAL);

    detect_idx_kernel<<<1, 1>>>((const unsigned int*)eidx);
    edge_mlp_kernel<<<tiles, 256, SM_TOTAL>>>(emb, eidx, W1, b1, W2, b2, out, E);
}